// round 16
// baseline (speedup 1.0000x reference)
#include <cuda_runtime.h>
#include <cuda_fp16.h>
#include <math.h>
#include <stdint.h>

#define DIMW 128
#define NG   100000
#define AS_B 272              // bytes per fp16 row of Ah/W (128*2 + 16 pad)
#define ST_B 264              // bytes per sT row [m][n] (128*2 + 8 pad)

// ---------------- scratch (no allocs) ----------------
__device__ float g_pool[(size_t)NG * DIMW];
__device__ float g_cnt[NG];
__device__ int   g_is64;
__device__ int   g_ticket;
__device__ __half g_WTh[3 * 128 * 128];   // W{1,2,3}^T fp16  [n][k]

// ---------------- kAtom smem layout (bytes) ----------------
#define SM_GID   0             // int[2][128] = 1024
#define SM_B1    1024          // float[128] = 512
#define SM_TK    1536          // int ticket broadcast
#define SM_W     1664          // W fp16: 34816 -> ends 36480
#define SM_A     36480         // Ah 34816 -> ends 71296
#define SM_ST    71296         // sT fp16 [m][n] 128x264B = 33792 -> ends 105088
#define SMEM_ATOM 105088

// ---------------- fused kGraph smem layout ----------------
#define GF_C     0             // cnt 512
#define GF_V     512           // W4 512
#define GF_B2    1024          // b2 512
#define GF_B3    1536          // b3 512
#define GF_P     2048          // partials 1024
#define GF_W2    3072          // 34816 -> 37888
#define GF_W3    37888         // 34816 -> 72704
#define GF_A     72704         // Ah 34816 -> 107520
#define SMEM_GF  107520

__device__ __forceinline__ uint32_t smem_u32(const void* p) {
    uint32_t a;
    asm("{ .reg .u64 t; cvta.to.shared.u64 t, %1; cvt.u32.u64 %0, t; }" : "=r"(a) : "l"(p));
    return a;
}
__device__ __forceinline__ void ldsm4(uint32_t& r0, uint32_t& r1, uint32_t& r2, uint32_t& r3,
                                      uint32_t addr) {
    asm volatile("ldmatrix.sync.aligned.m8n8.x4.shared.b16 {%0,%1,%2,%3}, [%4];"
                 : "=r"(r0), "=r"(r1), "=r"(r2), "=r"(r3) : "r"(addr));
}
__device__ __forceinline__ void mma16816(float* c, const uint32_t* a, uint32_t b0, uint32_t b1) {
    asm volatile("mma.sync.aligned.m16n8k16.row.col.f32.f16.f16.f32 "
                 "{%0,%1,%2,%3}, {%4,%5,%6,%7}, {%8,%9}, {%0,%1,%2,%3};"
                 : "+f"(c[0]), "+f"(c[1]), "+f"(c[2]), "+f"(c[3])
                 : "r"(a[0]), "r"(a[1]), "r"(a[2]), "r"(a[3]), "r"(b0), "r"(b1));
}

// ---------------------------------------------------------------------------
// 1-pass fp16 warp-tile core: 16 rows x 64 cols per warp, 16 warps = 128x128
// ---------------------------------------------------------------------------
__device__ __forceinline__ void mma_1pass(uint32_t A, uint32_t W, float acc[4][8]) {
    const int t = threadIdx.x, w = t >> 5, lane = t & 31;
    const int wm = w >> 1, wn = w & 1;
    const int lm = lane & 7, q = lane >> 3;
    const uint32_t aOff = (uint32_t)((wm * 16 + lm + (q & 1) * 8) * AS_B + ((q >> 1) * 8) * 2);
    const uint32_t bOff = (uint32_t)((wn * 64 + lm + (q >> 1) * 8) * AS_B + ((q & 1) * 8) * 2);
    const uint32_t Ah = A + aOff, Bb = W + bOff;
    #pragma unroll
    for (int kk = 0; kk < 8; kk++) {
        uint32_t ah[4], b[4][4];
        ldsm4(ah[0], ah[1], ah[2], ah[3], Ah + kk * 32);
        #pragma unroll
        for (int nb = 0; nb < 4; nb++)
            ldsm4(b[nb][0], b[nb][1], b[nb][2], b[nb][3], Bb + nb * 16 * AS_B + kk * 32);
        #pragma unroll
        for (int nb = 0; nb < 4; nb++) {
            mma16816(acc[nb],     ah, b[nb][0], b[nb][1]);
            mma16816(acc[nb] + 4, ah, b[nb][2], b[nb][3]);
        }
    }
}

// stage one prepped fp16 weight matrix into padded smem (NT threads)
template <int NT>
__device__ __forceinline__ void stage_W(char* sm, uint32_t wOff, int widx, int t) {
    for (int i = t; i < 256; i += NT) {
        const int r = i >> 1, h = i & 1;
        const uint4* ws = (const uint4*)(g_WTh + widx * 16384 + r * 128 + h * 64);
        char* d = sm + wOff + r * AS_B + h * 128;
        #pragma unroll
        for (int j = 0; j < 8; j++) ((uint4*)d)[j] = ws[j];
    }
}

// fp16 round-only store at (row m, float4-col c)  [kGraphF uses this]
__device__ __forceinline__ void round_store(float4 x, char* dstH, int m, int c) {
    __half2 hp0 = __halves2half2(__float2half_rn(x.x), __float2half_rn(x.y));
    __half2 hp1 = __halves2half2(__float2half_rn(x.z), __float2half_rn(x.w));
    *(uint2*)(dstH + m * AS_B + c * 8) = make_uint2(*(uint32_t*)&hp0, *(uint32_t*)&hp1);
}
// two float4 -> one uint4 fp16 store at (row m, 8-float chunk c8)
__device__ __forceinline__ void round_store8(float4 x0, float4 x1, char* dstH, int m, int c8) {
    __half2 a0 = __halves2half2(__float2half_rn(x0.x), __float2half_rn(x0.y));
    __half2 a1 = __halves2half2(__float2half_rn(x0.z), __float2half_rn(x0.w));
    __half2 a2 = __halves2half2(__float2half_rn(x1.x), __float2half_rn(x1.y));
    __half2 a3 = __halves2half2(__float2half_rn(x1.z), __float2half_rn(x1.w));
    *(uint4*)(dstH + m * AS_B + c8 * 16) =
        make_uint4(*(uint32_t*)&a0, *(uint32_t*)&a1, *(uint32_t*)&a2, *(uint32_t*)&a3);
}

// ---------------------------------------------------------------------------
// kInit: zero pool+cnt+ticket, detect batch dtype, prep fp16 weights
// ---------------------------------------------------------------------------
__global__ void kInit(const int* __restrict__ batch32, int n,
                      const float* __restrict__ W1, const float* __restrict__ W2,
                      const float* __restrict__ W3) {
    size_t i = (size_t)blockIdx.x * blockDim.x + threadIdx.x;
    const size_t pool4 = (size_t)NG * DIMW / 4;
    if (i < pool4)
        ((float4*)g_pool)[i] = make_float4(0.f, 0.f, 0.f, 0.f);
    else if (i < pool4 + NG)
        g_cnt[i - pool4] = 0.0f;
    if (i < 3 * 16384) {
        int widx = (int)(i >> 14), e = (int)(i & 16383);
        int nn = e >> 7, kk = e & 127;
        const float* W = (widx == 0) ? W1 : (widx == 1) ? W2 : W3;
        g_WTh[i] = __float2half_rn(W[kk * 128 + nn]);
    }
    if (i == 0) {
        g_is64 = (batch32[n - 1] == 0) ? 1 : 0;
        g_ticket = 0;
    }
}

// ---------------------------------------------------------------------------
// convert tile -> Ah + passthrough + gid slot p
// thread owns 8-float chunk c8 of row m; 4 row-iters; MLP-4 batched
// ---------------------------------------------------------------------------
__device__ __forceinline__ void convert_tile(
    const float* __restrict__ feat, float* __restrict__ outFeat,
    const void* __restrict__ batch, int is64, long long n,
    long long tile, char* sm, int p, int t)
{
    const int c8 = t & 15, mb = t >> 4;   // mb 0..31, 4 iters of 32 rows
    #pragma unroll
    for (int b = 0; b < 2; b++) {
        float4 x[4];
        #pragma unroll
        for (int jj = 0; jj < 2; jj++) {
            const int m = mb + (b * 2 + jj) * 32;
            long long row = tile * 128 + m;
            const float4* src = ((const float4*)(feat + (size_t)(row < n ? row : 0) * 128)) + c8 * 2;
            x[jj * 2]     = (row < n) ? __ldcs(src)     : make_float4(0.f, 0.f, 0.f, 0.f);
            x[jj * 2 + 1] = (row < n) ? __ldcs(src + 1) : make_float4(0.f, 0.f, 0.f, 0.f);
        }
        #pragma unroll
        for (int jj = 0; jj < 2; jj++) {
            const int m = mb + (b * 2 + jj) * 32;
            long long row = tile * 128 + m;
            if (row < n) {
                float4* dst = ((float4*)(outFeat + (size_t)row * 128)) + c8 * 2;
                __stcs(dst, x[jj * 2]);
                __stcs(dst + 1, x[jj * 2 + 1]);
            }
            round_store8(x[jj * 2], x[jj * 2 + 1], sm + SM_A, m, c8);
        }
    }
    if (t < 128) {
        long long row = tile * 128 + t;
        int g = -1;
        if (row < n)
            g = is64 ? (int)((const long long*)batch)[row] : ((const int*)batch)[row];
        ((int*)(sm + SM_GID))[p * 128 + t] = g;
    }
}

// ---------------------------------------------------------------------------
// kAtomTC: persistent, 512 threads, 2 CTAs/SM, dynamic tile ticketing.
// sT row-major [m][n] fp16; reduce over dim-pairs (half2), 8 strips x 16 atoms.
// ---------------------------------------------------------------------------
__global__ void __launch_bounds__(512, 2) kAtomTC(
    const float* __restrict__ feat, const void* __restrict__ batch, int n,
    const float* __restrict__ b1, float* __restrict__ outFeat, int ntiles)
{
    extern __shared__ char sm[];
    const uint32_t smb = smem_u32(sm);
    const int t = threadIdx.x, lane = t & 31, w = t >> 5;
    const int wm = w >> 1, wn = w & 1;
    const int is64 = g_is64;

    if (t < 128) ((float*)(sm + SM_B1))[t] = b1[t];
    stage_W<512>(sm, SM_W, 0, t);

    // prologue: grab first tile
    if (t == 0) *(int*)(sm + SM_TK) = atomicAdd(&g_ticket, 1);
    __syncthreads();
    int i = *(const int*)(sm + SM_TK);
    if (i >= ntiles) return;

    convert_tile(feat, outFeat, batch, is64, n, i, sm, 0, t);
    int p = 0;

    while (true) {
        __syncthreads();   // Ah(i)+gid(i) visible; sT(prev) fully reduced

        // 1) mma (1-pass) + grab next ticket + epilogue into sT [m][n]
        float acc[4][8];
        #pragma unroll
        for (int a = 0; a < 4; a++)
            #pragma unroll
            for (int b = 0; b < 8; b++) acc[a][b] = 0.0f;
        if (t == 0) *(int*)(sm + SM_TK) = atomicAdd(&g_ticket, 1);
        mma_1pass(smb + SM_A, smb + SM_W, acc);

        {
            char* sT = sm + SM_ST;
            const float* sB1 = (const float*)(sm + SM_B1);
            #pragma unroll
            for (int nb = 0; nb < 4; nb++) {
                #pragma unroll
                for (int g = 0; g < 2; g++) {
                    const int n0 = wn * 64 + nb * 16 + g * 8 + (lane & 3) * 2;
                    const int r0 = wm * 16 + (lane >> 2);
                    #pragma unroll
                    for (int mh = 0; mh < 2; mh++) {
                        const int mm = r0 + mh * 8;
                        float x0 = acc[nb][g * 4 + mh * 2 + 0] + sB1[n0];
                        float x1 = acc[nb][g * 4 + mh * 2 + 1] + sB1[n0 + 1];
                        float s0 = x0 * __fdividef(1.0f, 1.0f + __expf(-x0));
                        float s1 = x1 * __fdividef(1.0f, 1.0f + __expf(-x1));
                        __half2 hv = __halves2half2(__float2half_rn(s0), __float2half_rn(s1));
                        *(uint32_t*)(sT + mm * ST_B + n0 * 2) = *(uint32_t*)&hv;
                    }
                }
            }
        }
        __syncthreads();   // sT(i) + ticket visible; Ah free

        const int inext = *(const int*)(sm + SM_TK);
        const bool more = inext < ntiles;

        // 2) convert(inext) into Ah + gid slot p^1
        if (more)
            convert_tile(feat, outFeat, batch, is64, n, inext, sm, p ^ 1, t);

        // 3) segment reduce of sT: thread owns dim-pair dp, strip s of 16 atoms
        const int dp = t & 63, s = t >> 6;
        const int mS = s * 16;
        const int* gid = (const int*)(sm + SM_GID) + p * 128;
        const char* sT = sm + SM_ST;
        float2 run = make_float2(0.0f, 0.0f);
        int len = 0, cur = gid[mS];
        #pragma unroll 4
        for (int it = 0; it < 16; ++it) {
            const int mm = mS + it;
            int g = gid[mm];
            if (g != cur) {
                if (cur >= 0) {
                    atomicAdd(&g_pool[(size_t)cur * 128 + dp * 2], run.x);
                    atomicAdd(&g_pool[(size_t)cur * 128 + dp * 2 + 1], run.y);
                    if (dp == 0) atomicAdd(&g_cnt[cur], (float)len);
                }
                run = make_float2(0.0f, 0.0f); len = 0; cur = g;
            }
            if (g >= 0) {
                __half2 hv = *(const __half2*)(sT + mm * ST_B + dp * 4);
                float2 fv = __half22float2(hv);
                run.x += fv.x; run.y += fv.y; len++;
            }
        }
        if (cur >= 0) {
            atomicAdd(&g_pool[(size_t)cur * 128 + dp * 2], run.x);
            atomicAdd(&g_pool[(size_t)cur * 128 + dp * 2 + 1], run.y);
            if (dp == 0) atomicAdd(&g_cnt[cur], (float)len);
        }

        if (!more) break;
        i = inext;
        p ^= 1;
    }
}

// ---------------------------------------------------------------------------
// kGraphF: fused graph head, 1-pass both GEMMs, no intermediate round-trip.
// ---------------------------------------------------------------------------
__global__ void __launch_bounds__(512, 2) kGraphF(
    const float* __restrict__ b2, const float* __restrict__ b3,
    const float* __restrict__ W4, const float* __restrict__ b4,
    float* __restrict__ outS)
{
    extern __shared__ char sm[];
    const uint32_t smb = smem_u32(sm);
    const int t = threadIdx.x, lane = t & 31, w = t >> 5;
    const int wm = w >> 1, wn = w & 1;
    const int a0 = blockIdx.x * 128;
    const int mb = t >> 5, c = t & 31;

    float* sCnt = (float*)(sm + GF_C);
    float* sV   = (float*)(sm + GF_V);
    float* sB2  = (float*)(sm + GF_B2);
    float* sB3  = (float*)(sm + GF_B3);
    float* sP   = (float*)(sm + GF_P);
    if (t < 128) {
        sCnt[t] = (a0 + t < NG) ? g_cnt[a0 + t] : 0.0f;
        sV[t]  = W4[t];
        sB2[t] = b2[t];
        sB3[t] = b3[t];
    }
    stage_W<512>(sm, GF_W2, 1, t);
    stage_W<512>(sm, GF_W3, 2, t);
    #pragma unroll
    for (int j = 0; j < 8; j++) {
        const int m = mb + j * 16;
        int row = a0 + m;
        float4 x = (row < NG) ? ((const float4*)(g_pool + (size_t)row * 128))[c]
                              : make_float4(0.f, 0.f, 0.f, 0.f);
        round_store(x, sm + GF_A, m, c);
    }
    __syncthreads();

    // GEMM2: pooled @ W2
    float acc[4][8];
    #pragma unroll
    for (int a = 0; a < 4; a++)
        #pragma unroll
        for (int b = 0; b < 8; b++) acc[a][b] = 0.0f;
    mma_1pass(smb + GF_A, smb + GF_W2, acc);
    __syncthreads();   // done reading Ah

    // epilogue: h2 = acc + cnt*b2 -> fp16 back into Ah
    {
        char* Ah = sm + GF_A;
        #pragma unroll
        for (int nb = 0; nb < 4; nb++) {
            #pragma unroll
            for (int g = 0; g < 2; g++) {
                const int n0 = wn * 64 + nb * 16 + g * 8 + (lane & 3) * 2;
                const int r0 = wm * 16 + (lane >> 2);
                #pragma unroll
                for (int rr = 0; rr < 2; rr++) {
                    const int m = r0 + rr * 8;
                    float cn = sCnt[m];
                    float v0 = acc[nb][g * 4 + rr * 2 + 0] + cn * sB2[n0];
                    float v1 = acc[nb][g * 4 + rr * 2 + 1] + cn * sB2[n0 + 1];
                    __half2 hv = __halves2half2(__float2half_rn(v0), __float2half_rn(v1));
                    *(uint32_t*)(Ah + m * AS_B + n0 * 2) = *(uint32_t*)&hv;
                }
            }
        }
    }
    __syncthreads();   // h2 visible

    // GEMM3: h2 @ W3
    #pragma unroll
    for (int a = 0; a < 4; a++)
        #pragma unroll
        for (int b = 0; b < 8; b++) acc[a][b] = 0.0f;
    mma_1pass(smb + GF_A, smb + GF_W3, acc);

    // head: +b3, silu, x W4, reduce over dims
    float s0 = 0.0f, s1 = 0.0f;
    #pragma unroll
    for (int nb = 0; nb < 4; nb++) {
        #pragma unroll
        for (int g = 0; g < 2; g++) {
            const int n0 = wn * 64 + nb * 16 + g * 8 + (lane & 3) * 2;
            #pragma unroll
            for (int j = 0; j < 4; j++) {
                const int nn = n0 + (j & 1);
                float x = acc[nb][g * 4 + j] + sB3[nn];
                float h = x * __fdividef(1.0f, 1.0f + __expf(-x));
                float p = h * sV[nn];
                if (j < 2) s0 += p; else s1 += p;
            }
        }
    }
    s0 += __shfl_xor_sync(0xFFFFFFFF, s0, 1);
    s0 += __shfl_xor_sync(0xFFFFFFFF, s0, 2);
    s1 += __shfl_xor_sync(0xFFFFFFFF, s1, 1);
    s1 += __shfl_xor_sync(0xFFFFFFFF, s1, 2);
    if ((lane & 3) == 0) {
        const int mr = wm * 16 + (lane >> 2);
        sP[wn * 128 + mr] = s0;
        sP[wn * 128 + mr + 8] = s1;
    }
    __syncthreads();
    if (t < 128) {
        int row = a0 + t;
        if (row < NG) outS[row] = sP[t] + sP[128 + t] + b4[0];
    }
}

// ---------------------------------------------------------------------------
extern "C" void kernel_launch(void* const* d_in, const int* in_sizes, int n_in,
                              void* d_out, int out_size)
{
    const float* feat  = (const float*)d_in[0];
    const void*  batch = d_in[1];
    const float* W1 = (const float*)d_in[2];
    const float* b1 = (const float*)d_in[3];
    const float* W2 = (const float*)d_in[4];
    const float* b2 = (const float*)d_in[5];
    const float* W3 = (const float*)d_in[6];
    const float* b3 = (const float*)d_in[7];
    const float* W4 = (const float*)d_in[8];
    const float* b4 = (const float*)d_in[9];

    const int n = in_sizes[0] / DIMW;
    float* outS    = (float*)d_out;
    float* outFeat = (float*)d_out + NG;

    cudaFuncSetAttribute(kAtomTC, cudaFuncAttributeMaxDynamicSharedMemorySize, SMEM_ATOM);
    cudaFuncSetAttribute(kGraphF, cudaFuncAttributeMaxDynamicSharedMemorySize, SMEM_GF);

    {
        size_t total = (size_t)NG * DIMW / 4 + NG;
        kInit<<<(int)((total + 255) / 256), 256>>>((const int*)batch, n, W1, W2, W3);
    }
    {
        int ntiles = (n + 127) / 128;
        kAtomTC<<<296, 512, SMEM_ATOM>>>(feat, batch, n, b1, outFeat, ntiles);
    }
    {
        int grid = (NG + 127) / 128;
        kGraphF<<<grid, 512, SMEM_GF>>>(b2, b3, W4, b4, outS);
    }
}